// round 2
// baseline (speedup 1.0000x reference)
#include <cuda_runtime.h>

// SparseBiasDiagUnfolder: pure gather.
//   adj: (B=2, N=2048, N=2048, F=16) float32
//   starts = 0,4,...,2040 (511), off-diag positions = 56, out (2, 511, 896)
//
// R2: latency-bound fix. Each thread handles ITEMS=4 float4s strided by the
// total thread count: 4 independent LDG.128 batched up front (MLP_p1=4),
// stores remain fully coalesced (out float4 index == item index).
// Loads are made unconditional by clamping the index; only stores predicated.

namespace {
constexpr int B        = 2;
constexpr int N        = 2048;
constexpr int F        = 16;
constexpr int STRIDE   = 4;
constexpr int NSTARTS  = 511;
constexpr int NPOS     = 56;
constexpr int TOTAL_VEC = B * NSTARTS * NPOS * (F / 4);   // 228,928 float4s
constexpr int ITEMS    = 4;
constexpr int THREADS  = 256;
constexpr int NTHREADS_TOTAL = (TOTAL_VEC + ITEMS - 1) / ITEMS;          // 57,232
constexpr int BLOCKS   = (NTHREADS_TOTAL + THREADS - 1) / THREADS;       // 224
constexpr int TSTRIDE  = BLOCKS * THREADS;                               // 57,344
}

__device__ __forceinline__ long vec_addr(int idx)
{
    // idx = float4 index into out; decompose to (b, s, pos, v)
    int v   = idx & 3;
    int t   = idx >> 2;
    int pos = t % NPOS;
    int bs  = t / NPOS;
    int s   = bs % NSTARTS;
    int b   = bs / NSTARTS;

    int local = pos + 1 + (pos >> 3);   // skip diagonal (local % 9 == 0)
    int ii = local >> 3;
    int jj = local & 7;

    long base_f = ((long)b * N * N
                 + (long)(s * STRIDE) * (N + 1)
                 + (long)ii * N + jj) * F;
    return (base_f >> 2) + v;           // float4 index into adj
}

__global__ void __launch_bounds__(THREADS)
sparse_diag_unfold_kernel(const float4* __restrict__ adj, float4* __restrict__ out)
{
    const int tid = blockIdx.x * THREADS + threadIdx.x;

    float4 vals[ITEMS];

    // Batch all loads up front — unconditional (clamped), independent.
    #pragma unroll
    for (int k = 0; k < ITEMS; k++) {
        int idx = tid + k * TSTRIDE;
        int cidx = idx < TOTAL_VEC ? idx : (TOTAL_VEC - 1);
        vals[k] = adj[vec_addr(cidx)];
    }

    // Coalesced stores (consecutive lanes -> consecutive float4s).
    #pragma unroll
    for (int k = 0; k < ITEMS; k++) {
        int idx = tid + k * TSTRIDE;
        if (idx < TOTAL_VEC) out[idx] = vals[k];
    }
}

extern "C" void kernel_launch(void* const* d_in, const int* in_sizes, int n_in,
                              void* d_out, int out_size)
{
    const float4* adj = (const float4*)d_in[0];
    float4* out = (float4*)d_out;
    sparse_diag_unfold_kernel<<<BLOCKS, THREADS>>>(adj, out);
}